// round 15
// baseline (speedup 1.0000x reference)
#include <cuda_runtime.h>
#include <cstdint>

#define Hh   128
#define Ww   240
#define NG   40
#define CPG  8
#define ND   48
#define NCC  12
#define WQ   60

#define PSTRIDE 40                         // bytes per position in SMEM
#define PADPOS  48                         // zero positions in front (p < 0)
#define GWC_CTAS (NG * Hh)                 // 5120
#define CAT_CTAS (Hh * (ND / 8))           // 768 (d-groups of 8)
#define TOTAL_CTAS (GWC_CTAS + CAT_CTAS)   // 5888 = 256 * 23

// ---------------------------------------------------------------------------
// GWC: out[g][d][h][w] = (1/8) sum_c ref[gc][h][w] * tgt[gc][h][w-d]
// 128-thread CTA per (g,h); thread owns 2 consecutive w. Packed f32x2 FMA.
// SMEM tgt layout (R9, proven): position p at byte 40p, channels 0..7 at +4c.
// Front 48 positions are zero-filled so the sliding-window refill is a
// branch-free unconditional 4xLDS.64 (reads zeros for out-of-range p).
// ---------------------------------------------------------------------------
__device__ __forceinline__ void gwc_part(
    unsigned char* smem_raw, int g, int h, int tid,
    const float* __restrict__ refg, const float* __restrict__ tgtg,
    float* __restrict__ out)
{
    unsigned char* smem = smem_raw + PADPOS * PSTRIDE;  // position-0 base

    // Zero the pad region (positions -48..-1).
    for (int i = tid; i < (PADPOS * PSTRIDE) / 4; i += 128)
        ((float*)smem_raw)[i] = 0.f;

    // Stage tgt group-row, cc-major (conflict-light STS.32, proven R9).
    {
        const float* tb = tgtg + ((size_t)(g * CPG) * Hh + h) * Ww;
        for (int i = tid; i < CPG * WQ; i += 128) {
            int cc = i & 7;
            int q  = i >> 3;
            float4 v = *(const float4*)(tb + (size_t)cc * Hh * Ww + 4 * q);
            unsigned char* base = smem + cc * 4 + PSTRIDE * 4 * q;
            *(float*)(base + 0 * PSTRIDE) = v.x;
            *(float*)(base + 1 * PSTRIDE) = v.y;
            *(float*)(base + 2 * PSTRIDE) = v.z;
            *(float*)(base + 3 * PSTRIDE) = v.w;
        }
    }

    const int  t   = tid;
    const bool act = (t < 120);

    // rt64[j][p] = (ref[c=2p](w=2t+j), ref[c=2p+1](w=2t+j)) * 1/8, packed f32x2.
    unsigned long long rt64[2][4];
    if (act) {
        const float* rb = refg + ((size_t)(g * CPG) * Hh + h) * Ww + 2 * t;
        float2 rch[8];
#pragma unroll
        for (int cc = 0; cc < 8; cc++)
            rch[cc] = *(const float2*)(rb + (size_t)cc * Hh * Ww);
#pragma unroll
        for (int p = 0; p < 4; p++) {
            asm("mov.b64 %0, {%1, %2};" : "=l"(rt64[0][p])
                : "f"(rch[2 * p].x * 0.125f), "f"(rch[2 * p + 1].x * 0.125f));
            asm("mov.b64 %0, {%1, %2};" : "=l"(rt64[1][p])
                : "f"(rch[2 * p].y * 0.125f), "f"(rch[2 * p + 1].y * 0.125f));
        }
    }
    __syncthreads();
    if (!act) return;

    // Invariant: win[(j - d) & 1][p] = f32x2 pair p of tgt[2t + j - d].
    unsigned long long win[2][4];
#pragma unroll
    for (int k = 0; k < 2; k++) {
        const unsigned char* base = smem + PSTRIDE * (2 * t + k);
#pragma unroll
        for (int p = 0; p < 4; p++)
            win[k][p] = *(const unsigned long long*)(base + 8 * p);
    }

    // Running refill byte offset: position (2t - d - 1) at step d.
    // Minimum over the loop: (0 - 47 - 1)*40 = -1920 = -PADPOS*PSTRIDE: in-pad.
    int rb_off = (2 * t - 1) * PSTRIDE;

    float* op = out + (((size_t)g * ND) * Hh + h) * Ww + 2 * t;
#pragma unroll
    for (int d = 0; d < ND; d++) {
        float2 o;
#pragma unroll
        for (int j = 0; j < 2; j++) {
            const int k = (j - d) & 1;
            unsigned long long acc;
            asm("mul.rn.f32x2 %0, %1, %2;"
                : "=l"(acc) : "l"(rt64[j][0]), "l"(win[k][0]));
            asm("fma.rn.f32x2 %0, %1, %2, %3;"
                : "=l"(acc) : "l"(rt64[j][1]), "l"(win[k][1]), "l"(acc));
            asm("fma.rn.f32x2 %0, %1, %2, %3;"
                : "=l"(acc) : "l"(rt64[j][2]), "l"(win[k][2]), "l"(acc));
            asm("fma.rn.f32x2 %0, %1, %2, %3;"
                : "=l"(acc) : "l"(rt64[j][3]), "l"(win[k][3]), "l"(acc));
            float lo, hi;
            asm("mov.b64 {%0, %1}, %2;" : "=f"(lo), "=f"(hi) : "l"(acc));
            if (j == 0) o.x = lo + hi; else o.y = lo + hi;
        }
        *(float2*)op = o;
        op += (size_t)Hh * Ww;

        if (d < ND - 1) {
            const int slot = (d + 1) & 1;
            const unsigned char* base = smem + rb_off;   // branch-free
#pragma unroll
            for (int p = 0; p < 4; p++)
                win[slot][p] = *(const unsigned long long*)(base + 8 * p);
            rb_off -= PSTRIDE;
        }
    }
}

// ---------------------------------------------------------------------------
// Concat: CTA per (h, grp) covering d = 8*grp .. 8*grp+7.
// Three tgt float4 loads + one ref load serve 8 d-planes each.
// ---------------------------------------------------------------------------
__device__ __forceinline__ void cat_part(
    int h, int grp, int t,
    const float* __restrict__ rc, const float* __restrict__ tc,
    float* __restrict__ out)
{
    if (t >= 120) return;
    const int half = (t >= 60) ? 1 : 0;
    const int q    = t - 60 * half;
    const int wb   = 4 * q;
    const int d0   = 8 * grp;
    const size_t hw = (size_t)Hh * Ww;

#pragma unroll
    for (int i = 0; i < 12; i++) {
        const int cc = half + 2 * i;      // 0..23
        float* ob = out + ((size_t)(NG + cc) * ND + d0) * hw + (size_t)h * Ww + wb;

        if (i < 6) {
            // ref channel cc: one load, 8 masked stores
            float4 v = *(const float4*)(rc + ((size_t)cc * Hh + h) * Ww + wb);
#pragma unroll
            for (int t2 = 0; t2 < 8; t2++) {
                const int d = d0 + t2;
                float4 o;
                o.x = (wb + 0 >= d) ? v.x : 0.f;
                o.y = (wb + 1 >= d) ? v.y : 0.f;
                o.z = (wb + 2 >= d) ? v.z : 0.f;
                o.w = (wb + 3 >= d) ? v.w : 0.f;
                *(float4*)(ob + (size_t)t2 * hw) = o;
            }
        } else {
            // tgt channel cc-12: three loads serve 8 shifted stores
            const int ch = cc - NCC;
            const float* row = tc + ((size_t)ch * Hh + h) * Ww;
            const int c2 = q - 2 * grp, c1 = c2 - 1, c0 = c2 - 2;
            float4 v2 = (c2 >= 0) ? *(const float4*)(row + 4 * c2)
                                  : make_float4(0.f, 0.f, 0.f, 0.f);
            float4 v1 = (c1 >= 0) ? *(const float4*)(row + 4 * c1)
                                  : make_float4(0.f, 0.f, 0.f, 0.f);
            float4 v0 = (c0 >= 0) ? *(const float4*)(row + 4 * c0)
                                  : make_float4(0.f, 0.f, 0.f, 0.f);
            const float arr[12] = {v0.x, v0.y, v0.z, v0.w,
                                   v1.x, v1.y, v1.z, v1.w,
                                   v2.x, v2.y, v2.z, v2.w};
#pragma unroll
            for (int t2 = 0; t2 < 8; t2++) {
                float4 o;
                o.x = arr[8 - t2];
                o.y = arr[9 - t2];
                o.z = arr[10 - t2];
                o.w = arr[11 - t2];
                *(float4*)(ob + (size_t)t2 * hw) = o;
            }
        }
    }
}

// ---------------------------------------------------------------------------
__global__ void __launch_bounds__(128, 10) fused_kernel(
    const float* __restrict__ refg, const float* __restrict__ tgtg,
    const float* __restrict__ rc,   const float* __restrict__ tc,
    float* __restrict__ out)
{
    __shared__ __align__(16) unsigned char smem[(PADPOS + Ww) * PSTRIDE]; // 11520B

    const int bx  = blockIdx.x;
    const int tid = threadIdx.x;
    const int qq  = bx / 23;
    const int r   = bx - qq * 23;

    if (r < 20) {
        const int idx = qq * 20 + r;         // 0..5119
        gwc_part(smem, idx / Hh, idx % Hh, tid, refg, tgtg, out);
    } else {
        const int idx = qq * 3 + (r - 20);   // 0..767
        cat_part(idx % Hh, idx / Hh, tid, rc, tc, out);
    }
}

extern "C" void kernel_launch(void* const* d_in, const int* in_sizes, int n_in,
                              void* d_out, int out_size)
{
    const float* refg = (const float*)d_in[0];  // ref_gwc    [320,128,240]
    const float* tgtg = (const float*)d_in[1];  // tgt_gwc    [320,128,240]
    const float* rc   = (const float*)d_in[2];  // ref_concat [12,128,240]
    const float* tc   = (const float*)d_in[3];  // tgt_concat [12,128,240]
    float* out = (float*)d_out;                 // [64,48,128,240]

    fused_kernel<<<TOTAL_CTAS, 128>>>(refg, tgtg, rc, tc, out);
}

// round 16
// speedup vs baseline: 1.4122x; 1.4122x over previous
#include <cuda_runtime.h>
#include <cstdint>

#define Hh   128
#define Ww   240
#define NG   40
#define CPG  8
#define ND   48
#define NCC  12
#define WQ   60

#define PSTRIDE 40                         // bytes per position in SMEM
#define GWC_CTAS (NG * Hh)                 // 5120
#define CAT_CTAS (Hh * (ND / 8))           // 768 (d-groups of 8)
#define TOTAL_CTAS (GWC_CTAS + CAT_CTAS)   // 5888 = 256 * 23

// ---------------------------------------------------------------------------
// GWC: out[g][d][h][w] = (1/8) sum_c ref[gc][h][w] * tgt[gc][h][w-d]
// 128-thread CTA per (g,h); thread owns 2 consecutive w. Packed f32x2 FMA.
// SMEM tgt layout (R9, proven): position p at byte 40p, channels 0..7 at +4c.
// Conditional 4xLDS.64 refill per d — DO NOT restructure (R12/R13/R14 all
// regressed when this loop's addressing was made "smarter").
// ---------------------------------------------------------------------------
__device__ __forceinline__ void gwc_part(
    unsigned char* smem, int g, int h, int tid,
    const float* __restrict__ refg, const float* __restrict__ tgtg,
    float* __restrict__ out)
{
    // Stage tgt group-row, cc-major (proven R9).
    {
        const float* tb = tgtg + ((size_t)(g * CPG) * Hh + h) * Ww;
        for (int i = tid; i < CPG * WQ; i += 128) {
            int cc = i & 7;
            int q  = i >> 3;
            float4 v = *(const float4*)(tb + (size_t)cc * Hh * Ww + 4 * q);
            unsigned char* base = smem + cc * 4 + PSTRIDE * 4 * q;
            *(float*)(base + 0 * PSTRIDE) = v.x;
            *(float*)(base + 1 * PSTRIDE) = v.y;
            *(float*)(base + 2 * PSTRIDE) = v.z;
            *(float*)(base + 3 * PSTRIDE) = v.w;
        }
    }

    const int  t   = tid;
    const bool act = (t < 120);

    // rt64[j][p] = (ref[c=2p](w=2t+j), ref[c=2p+1](w=2t+j)) * 1/8, packed f32x2.
    unsigned long long rt64[2][4];
    if (act) {
        const float* rb = refg + ((size_t)(g * CPG) * Hh + h) * Ww + 2 * t;
        float2 rch[8];
#pragma unroll
        for (int cc = 0; cc < 8; cc++)
            rch[cc] = *(const float2*)(rb + (size_t)cc * Hh * Ww);
#pragma unroll
        for (int p = 0; p < 4; p++) {
            asm("mov.b64 %0, {%1, %2};" : "=l"(rt64[0][p])
                : "f"(rch[2 * p].x * 0.125f), "f"(rch[2 * p + 1].x * 0.125f));
            asm("mov.b64 %0, {%1, %2};" : "=l"(rt64[1][p])
                : "f"(rch[2 * p].y * 0.125f), "f"(rch[2 * p + 1].y * 0.125f));
        }
    }
    __syncthreads();
    if (!act) return;

    // Invariant: win[(j - d) & 1][p] = f32x2 pair p of tgt[2t + j - d].
    unsigned long long win[2][4];
#pragma unroll
    for (int k = 0; k < 2; k++) {
        const unsigned char* base = smem + PSTRIDE * (2 * t + k);
#pragma unroll
        for (int p = 0; p < 4; p++)
            win[k][p] = *(const unsigned long long*)(base + 8 * p);
    }

    // Running refill byte offset: position (2t - d - 1) at step d.
    int rb_off = (2 * t - 1) * PSTRIDE;

    float* op = out + (((size_t)g * ND) * Hh + h) * Ww + 2 * t;
#pragma unroll
    for (int d = 0; d < ND; d++) {
        float2 o;
#pragma unroll
        for (int j = 0; j < 2; j++) {
            const int k = (j - d) & 1;
            unsigned long long acc;
            asm("mul.rn.f32x2 %0, %1, %2;"
                : "=l"(acc) : "l"(rt64[j][0]), "l"(win[k][0]));
            asm("fma.rn.f32x2 %0, %1, %2, %3;"
                : "=l"(acc) : "l"(rt64[j][1]), "l"(win[k][1]), "l"(acc));
            asm("fma.rn.f32x2 %0, %1, %2, %3;"
                : "=l"(acc) : "l"(rt64[j][2]), "l"(win[k][2]), "l"(acc));
            asm("fma.rn.f32x2 %0, %1, %2, %3;"
                : "=l"(acc) : "l"(rt64[j][3]), "l"(win[k][3]), "l"(acc));
            float lo, hi;
            asm("mov.b64 {%0, %1}, %2;" : "=f"(lo), "=f"(hi) : "l"(acc));
            if (j == 0) o.x = lo + hi; else o.y = lo + hi;
        }
        *(float2*)op = o;
        op += (size_t)Hh * Ww;

        if (d < ND - 1) {
            const int slot = (d + 1) & 1;
            if (rb_off >= 0) {
                const unsigned char* base = smem + rb_off;
#pragma unroll
                for (int p = 0; p < 4; p++)
                    win[slot][p] = *(const unsigned long long*)(base + 8 * p);
            } else {
#pragma unroll
                for (int p = 0; p < 4; p++)
                    win[slot][p] = 0ull;
            }
            rb_off -= PSTRIDE;
        }
    }
}

// ---------------------------------------------------------------------------
// Concat: CTA per (h, grp) covering d = 8*grp .. 8*grp+7.
// Three tgt float4 loads + one ref load serve 8 d-planes each.
// arr[m] = tgt[wb - d0 - 8 + m]; plane t2 output j reads arr[8 + j - t2].
// ---------------------------------------------------------------------------
__device__ __forceinline__ void cat_part(
    int h, int grp, int t,
    const float* __restrict__ rc, const float* __restrict__ tc,
    float* __restrict__ out)
{
    if (t >= 120) return;
    const int half = (t >= 60) ? 1 : 0;
    const int q    = t - 60 * half;
    const int wb   = 4 * q;
    const int d0   = 8 * grp;
    const size_t hw = (size_t)Hh * Ww;

#pragma unroll
    for (int i = 0; i < 12; i++) {
        const int cc = half + 2 * i;      // 0..23
        float* ob = out + ((size_t)(NG + cc) * ND + d0) * hw + (size_t)h * Ww + wb;

        if (i < 6) {
            // ref channel cc: one load, 8 masked stores
            float4 v = *(const float4*)(rc + ((size_t)cc * Hh + h) * Ww + wb);
#pragma unroll
            for (int t2 = 0; t2 < 8; t2++) {
                const int d = d0 + t2;
                float4 o;
                o.x = (wb + 0 >= d) ? v.x : 0.f;
                o.y = (wb + 1 >= d) ? v.y : 0.f;
                o.z = (wb + 2 >= d) ? v.z : 0.f;
                o.w = (wb + 3 >= d) ? v.w : 0.f;
                *(float4*)(ob + (size_t)t2 * hw) = o;
            }
        } else {
            // tgt channel cc-12: three loads serve 8 shifted stores
            const int ch = cc - NCC;
            const float* row = tc + ((size_t)ch * Hh + h) * Ww;
            const int c2 = q - 2 * grp, c1 = c2 - 1, c0 = c2 - 2;
            float4 v2 = (c2 >= 0) ? *(const float4*)(row + 4 * c2)
                                  : make_float4(0.f, 0.f, 0.f, 0.f);
            float4 v1 = (c1 >= 0) ? *(const float4*)(row + 4 * c1)
                                  : make_float4(0.f, 0.f, 0.f, 0.f);
            float4 v0 = (c0 >= 0) ? *(const float4*)(row + 4 * c0)
                                  : make_float4(0.f, 0.f, 0.f, 0.f);
            const float arr[12] = {v0.x, v0.y, v0.z, v0.w,
                                   v1.x, v1.y, v1.z, v1.w,
                                   v2.x, v2.y, v2.z, v2.w};
#pragma unroll
            for (int t2 = 0; t2 < 8; t2++) {
                float4 o;
                o.x = arr[8 - t2];
                o.y = arr[9 - t2];
                o.z = arr[10 - t2];
                o.w = arr[11 - t2];
                *(float4*)(ob + (size_t)t2 * hw) = o;
            }
        }
    }
}

// ---------------------------------------------------------------------------
__global__ void __launch_bounds__(128, 10) fused_kernel(
    const float* __restrict__ refg, const float* __restrict__ tgtg,
    const float* __restrict__ rc,   const float* __restrict__ tc,
    float* __restrict__ out)
{
    __shared__ __align__(16) unsigned char smem[Ww * PSTRIDE];  // 9600B

    const int bx  = blockIdx.x;
    const int tid = threadIdx.x;
    const int qq  = bx / 23;
    const int r   = bx - qq * 23;

    if (r < 20) {
        const int idx = qq * 20 + r;         // 0..5119
        gwc_part(smem, idx / Hh, idx % Hh, tid, refg, tgtg, out);
    } else {
        const int idx = qq * 3 + (r - 20);   // 0..767
        cat_part(idx % Hh, idx / Hh, tid, rc, tc, out);
    }
}

extern "C" void kernel_launch(void* const* d_in, const int* in_sizes, int n_in,
                              void* d_out, int out_size)
{
    const float* refg = (const float*)d_in[0];  // ref_gwc    [320,128,240]
    const float* tgtg = (const float*)d_in[1];  // tgt_gwc    [320,128,240]
    const float* rc   = (const float*)d_in[2];  // ref_concat [12,128,240]
    const float* tc   = (const float*)d_in[3];  // tgt_concat [12,128,240]
    float* out = (float*)d_out;                 // [64,48,128,240]

    fused_kernel<<<TOTAL_CTAS, 128>>>(refg, tgtg, rc, tc, out);
}